// round 1
// baseline (speedup 1.0000x reference)
#include <cuda_runtime.h>

// Problem constants from the reference:
//   samples: [N_SAMPLES=16, B=4, C=1, H=256, W=256] fp32
//   target : [B, C, H, W] fp32
//   out    : scalar fp32 = mean_p( mean_i|s_i - y| - 0.5*mean_{i,j}|s_i - s_j| )
// With i<j symmetry: 0.5*mean_{i,j}|s_i-s_j| = (1/N^2) * sum_{i<j}|s_i - s_j|.

#define NS 16
#define PIXELS (4 * 1 * 256 * 256)   // 262144
#define TPB 256
#define NBLOCKS (PIXELS / TPB)       // 1024

__device__ float g_partials[NBLOCKS];

__global__ __launch_bounds__(TPB) void crps_main_kernel(
    const float* __restrict__ samples,   // [NS, PIXELS]
    const float* __restrict__ target,    // [PIXELS]
    float* __restrict__ partials)
{
    const int p = blockIdx.x * TPB + threadIdx.x;

    // Load ensemble for this pixel into registers (coalesced across threads).
    float v[NS];
#pragma unroll
    for (int i = 0; i < NS; i++)
        v[i] = samples[i * PIXELS + p];
    const float y = target[p];

    // term1 numerator: sum_i |v_i - y|
    float t1 = 0.f;
#pragma unroll
    for (int i = 0; i < NS; i++)
        t1 += fabsf(v[i] - y);

    // term2 numerator: sum_{i<j} |v_i - v_j|   (120 pairs)
    float t2 = 0.f;
#pragma unroll
    for (int i = 0; i < NS; i++)
#pragma unroll
        for (int j = i + 1; j < NS; j++)
            t2 += fabsf(v[i] - v[j]);

    // per-pixel CRPS contribution
    float crps = t1 * (1.f / NS) - t2 * (1.f / (NS * NS));

    // Block reduction: warp shuffle, then one value per warp through smem.
#pragma unroll
    for (int off = 16; off > 0; off >>= 1)
        crps += __shfl_down_sync(0xFFFFFFFFu, crps, off);

    __shared__ float warp_sums[TPB / 32];
    const int lane = threadIdx.x & 31;
    const int wid  = threadIdx.x >> 5;
    if (lane == 0) warp_sums[wid] = crps;
    __syncthreads();

    if (wid == 0) {
        float s = (lane < TPB / 32) ? warp_sums[lane] : 0.f;
#pragma unroll
        for (int off = 4; off > 0; off >>= 1)
            s += __shfl_down_sync(0xFFFFFFFFu, s, off);
        if (lane == 0) partials[blockIdx.x] = s;
    }
}

__global__ __launch_bounds__(TPB) void crps_final_kernel(
    const float* __restrict__ partials, float* __restrict__ out)
{
    // 1024 partials, 256 threads -> 4 each
    float s = 0.f;
#pragma unroll
    for (int k = 0; k < NBLOCKS / TPB; k++)
        s += partials[k * TPB + threadIdx.x];

#pragma unroll
    for (int off = 16; off > 0; off >>= 1)
        s += __shfl_down_sync(0xFFFFFFFFu, s, off);

    __shared__ float warp_sums[TPB / 32];
    const int lane = threadIdx.x & 31;
    const int wid  = threadIdx.x >> 5;
    if (lane == 0) warp_sums[wid] = s;
    __syncthreads();

    if (wid == 0) {
        float t = (lane < TPB / 32) ? warp_sums[lane] : 0.f;
#pragma unroll
        for (int off = 4; off > 0; off >>= 1)
            t += __shfl_down_sync(0xFFFFFFFFu, t, off);
        if (lane == 0) out[0] = t * (1.f / PIXELS);
    }
}

extern "C" void kernel_launch(void* const* d_in, const int* in_sizes, int n_in,
                              void* d_out, int out_size)
{
    const float* samples = (const float*)d_in[0];
    const float* target  = (const float*)d_in[1];
    float* out = (float*)d_out;

    float* partials;
    cudaGetSymbolAddress((void**)&partials, g_partials);

    crps_main_kernel<<<NBLOCKS, TPB>>>(samples, target, partials);
    crps_final_kernel<<<1, TPB>>>(partials, out);
}

// round 2
// speedup vs baseline: 1.0276x; 1.0276x over previous
#include <cuda_runtime.h>

// CRPS over a 16-member ensemble:
//   out = mean_p( (1/N) sum_i |s_i - y|  -  (1/N^2) sum_{i<j} |s_i - s_j| )
// Key identity: with v sorted ascending, sum_{i<j}|v_i - v_j| = sum_i (2i-15) v_i.
// Sorting 16 floats = Batcher odd-even merge network, 63 compare-exchanges
// (FMNMX pairs, alu pipe) vs 120 abs-diff pairs (240 fma-pipe ops).

#define NS 16
#define PIXELS (4 * 1 * 256 * 256)      // 262144
#define TPB 256
#define PPT 2                           // pixels per thread (float2 loads)
#define NTHREADS (PIXELS / PPT)         // 131072
#define NBLOCKS (NTHREADS / TPB)        // 512
#define HALF_PIXELS (PIXELS / 2)

__device__ float g_partials[NBLOCKS];
__device__ unsigned int g_count = 0;

__device__ __forceinline__ void cmpswap(float& a, float& b) {
    float lo = fminf(a, b);
    float hi = fmaxf(a, b);
    a = lo; b = hi;
}

// Per-pixel CRPS contribution (un-normalized by PIXELS).
__device__ __forceinline__ float crps_pixel(float (&v)[NS], float y) {
    // term1: sum_i |v_i - y|   (permutation-invariant; fma pipe)
    float t1 = 0.f;
#pragma unroll
    for (int i = 0; i < NS; i++)
        t1 += fabsf(v[i] - y);

    // Sort v ascending: Batcher odd-even mergesort, 16 inputs, 63 comparators.
#define CS(a, b) cmpswap(v[a], v[b])
    CS(0,1);  CS(2,3);  CS(4,5);  CS(6,7);  CS(8,9);  CS(10,11); CS(12,13); CS(14,15);
    CS(0,2);  CS(1,3);  CS(4,6);  CS(5,7);  CS(8,10); CS(9,11);  CS(12,14); CS(13,15);
    CS(1,2);  CS(5,6);  CS(9,10); CS(13,14);
    CS(0,4);  CS(1,5);  CS(2,6);  CS(3,7);  CS(8,12); CS(9,13);  CS(10,14); CS(11,15);
    CS(2,4);  CS(3,5);  CS(10,12); CS(11,13);
    CS(1,2);  CS(3,4);  CS(5,6);  CS(9,10); CS(11,12); CS(13,14);
    CS(0,8);  CS(1,9);  CS(2,10); CS(3,11); CS(4,12); CS(5,13);  CS(6,14);  CS(7,15);
    CS(4,8);  CS(5,9);  CS(6,10); CS(7,11);
    CS(2,4);  CS(3,5);  CS(6,8);  CS(7,9);  CS(10,12); CS(11,13);
    CS(1,2);  CS(3,4);  CS(5,6);  CS(7,8);  CS(9,10);  CS(11,12); CS(13,14);
#undef CS

    // term2: sum_{i<j} (v_j - v_i) = sum_i (2i - 15) v_i  (16 FFMA)
    float t2 = 0.f;
#pragma unroll
    for (int i = 0; i < NS; i++)
        t2 = fmaf((float)(2 * i - 15), v[i], t2);

    return t1 * (1.f / NS) - t2 * (1.f / (NS * NS));
}

__global__ __launch_bounds__(TPB) void crps_fused_kernel(
    const float2* __restrict__ samples,   // [NS, HALF_PIXELS] as float2
    const float2* __restrict__ target,    // [HALF_PIXELS] as float2
    float* __restrict__ out)
{
    const int t = blockIdx.x * TPB + threadIdx.x;

    // Load 16 ensemble members for two adjacent pixels (coalesced LDG.64).
    float2 s[NS];
#pragma unroll
    for (int i = 0; i < NS; i++)
        s[i] = samples[i * HALF_PIXELS + t];
    const float2 y = target[t];

    float vx[NS], vy[NS];
#pragma unroll
    for (int i = 0; i < NS; i++) { vx[i] = s[i].x; vy[i] = s[i].y; }

    float acc = crps_pixel(vx, y.x) + crps_pixel(vy, y.y);

    // ---- block reduction ----
#pragma unroll
    for (int off = 16; off > 0; off >>= 1)
        acc += __shfl_down_sync(0xFFFFFFFFu, acc, off);

    __shared__ float warp_sums[TPB / 32];
    const int lane = threadIdx.x & 31;
    const int wid  = threadIdx.x >> 5;
    if (lane == 0) warp_sums[wid] = acc;
    __syncthreads();

    __shared__ bool is_last;
    if (threadIdx.x == 0) {
        float bsum = 0.f;
#pragma unroll
        for (int w = 0; w < TPB / 32; w++)
            bsum += warp_sums[w];
        g_partials[blockIdx.x] = bsum;
        __threadfence();
        unsigned int done = atomicAdd(&g_count, 1u);
        is_last = (done == NBLOCKS - 1);
    }
    __syncthreads();

    // ---- last block folds all partials (fixed order -> deterministic) ----
    if (is_last) {
        float sred = g_partials[threadIdx.x] + g_partials[threadIdx.x + TPB];
#pragma unroll
        for (int off = 16; off > 0; off >>= 1)
            sred += __shfl_down_sync(0xFFFFFFFFu, sred, off);
        if (lane == 0) warp_sums[wid] = sred;
        __syncthreads();
        if (wid == 0) {
            float tot = (lane < TPB / 32) ? warp_sums[lane] : 0.f;
#pragma unroll
            for (int off = 4; off > 0; off >>= 1)
                tot += __shfl_down_sync(0xFFFFFFFFu, tot, off);
            if (lane == 0) {
                out[0] = tot * (1.f / PIXELS);
                g_count = 0;   // reset for next graph replay
            }
        }
    }
}

extern "C" void kernel_launch(void* const* d_in, const int* in_sizes, int n_in,
                              void* d_out, int out_size)
{
    const float2* samples = (const float2*)d_in[0];
    const float2* target  = (const float2*)d_in[1];
    float* out = (float*)d_out;

    crps_fused_kernel<<<NBLOCKS, TPB>>>(samples, target, out);
}

// round 3
// speedup vs baseline: 1.2362x; 1.2030x over previous
#include <cuda_runtime.h>

// CRPS over a 16-member ensemble:
//   out = mean_p( (1/N) sum_i |s_i - y|  -  (1/N^2) sum_{i<j} |s_i - s_j| )
// Identity: with v sorted ascending, sum_{i<j}|v_i - v_j| = sum_i (2i-15) v_i.
// Batcher odd-even mergesort (63 comparators = 126 FMNMX, alu pipe) replaces
// 120 abs-diff pairs (240 fma-pipe ops); term1 runs on the fma pipe in parallel.
//
// Shape: 1 pixel/thread, 262144 threads -> ~55 warps/SM for latency hiding.
// Single launch; last-block-finishes reduction (deterministic fixed-order sum).

#define NS 16
#define PIXELS (4 * 1 * 256 * 256)      // 262144
#define TPB 256
#define NBLOCKS (PIXELS / TPB)          // 1024

__device__ float g_partials[NBLOCKS];
__device__ unsigned int g_count = 0;

__device__ __forceinline__ void cmpswap(float& a, float& b) {
    float lo = fminf(a, b);
    float hi = fmaxf(a, b);
    a = lo; b = hi;
}

__global__ __launch_bounds__(TPB) void crps_fused_kernel(
    const float* __restrict__ samples,   // [NS, PIXELS]
    const float* __restrict__ target,    // [PIXELS]
    float* __restrict__ out)
{
    const int p = blockIdx.x * TPB + threadIdx.x;

    // Batch all 16 member loads (plus target) before any math -> MLP=17/warp.
    float v[NS];
#pragma unroll
    for (int i = 0; i < NS; i++)
        v[i] = samples[i * PIXELS + p];
    const float y = target[p];

    // term1: sum_i |v_i - y|  (permutation-invariant, fma pipe)
    float t1 = 0.f;
#pragma unroll
    for (int i = 0; i < NS; i++)
        t1 += fabsf(v[i] - y);

    // Sort v ascending: Batcher odd-even mergesort, 16 inputs, 63 comparators.
#define CS(a, b) cmpswap(v[a], v[b])
    CS(0,1);  CS(2,3);  CS(4,5);  CS(6,7);  CS(8,9);  CS(10,11); CS(12,13); CS(14,15);
    CS(0,2);  CS(1,3);  CS(4,6);  CS(5,7);  CS(8,10); CS(9,11);  CS(12,14); CS(13,15);
    CS(1,2);  CS(5,6);  CS(9,10); CS(13,14);
    CS(0,4);  CS(1,5);  CS(2,6);  CS(3,7);  CS(8,12); CS(9,13);  CS(10,14); CS(11,15);
    CS(2,4);  CS(3,5);  CS(10,12); CS(11,13);
    CS(1,2);  CS(3,4);  CS(5,6);  CS(9,10); CS(11,12); CS(13,14);
    CS(0,8);  CS(1,9);  CS(2,10); CS(3,11); CS(4,12); CS(5,13);  CS(6,14);  CS(7,15);
    CS(4,8);  CS(5,9);  CS(6,10); CS(7,11);
    CS(2,4);  CS(3,5);  CS(6,8);  CS(7,9);  CS(10,12); CS(11,13);
    CS(1,2);  CS(3,4);  CS(5,6);  CS(7,8);  CS(9,10);  CS(11,12); CS(13,14);
#undef CS

    // term2: sum_{i<j}(v_j - v_i) = sum_i (2i-15) v_i   (16 FFMA)
    float t2 = 0.f;
#pragma unroll
    for (int i = 0; i < NS; i++)
        t2 = fmaf((float)(2 * i - 15), v[i], t2);

    float acc = t1 * (1.f / NS) - t2 * (1.f / (NS * NS));

    // ---- block reduction ----
#pragma unroll
    for (int off = 16; off > 0; off >>= 1)
        acc += __shfl_down_sync(0xFFFFFFFFu, acc, off);

    __shared__ float warp_sums[TPB / 32];
    const int lane = threadIdx.x & 31;
    const int wid  = threadIdx.x >> 5;
    if (lane == 0) warp_sums[wid] = acc;
    __syncthreads();

    __shared__ bool is_last;
    if (threadIdx.x == 0) {
        float bsum = 0.f;
#pragma unroll
        for (int w = 0; w < TPB / 32; w++)
            bsum += warp_sums[w];
        g_partials[blockIdx.x] = bsum;
        __threadfence();
        unsigned int done = atomicAdd(&g_count, 1u);
        is_last = (done == NBLOCKS - 1);
    }
    __syncthreads();

    // ---- last block folds all 1024 partials in a fixed order ----
    if (is_last) {
        float s = 0.f;
#pragma unroll
        for (int k = 0; k < NBLOCKS / TPB; k++)
            s += g_partials[k * TPB + threadIdx.x];
#pragma unroll
        for (int off = 16; off > 0; off >>= 1)
            s += __shfl_down_sync(0xFFFFFFFFu, s, off);
        if (lane == 0) warp_sums[wid] = s;
        __syncthreads();
        if (wid == 0) {
            float tot = (lane < TPB / 32) ? warp_sums[lane] : 0.f;
#pragma unroll
            for (int off = 4; off > 0; off >>= 1)
                tot += __shfl_down_sync(0xFFFFFFFFu, tot, off);
            if (lane == 0) {
                out[0] = tot * (1.f / PIXELS);
                g_count = 0;   // reset for next graph replay
            }
        }
    }
}

extern "C" void kernel_launch(void* const* d_in, const int* in_sizes, int n_in,
                              void* d_out, int out_size)
{
    const float* samples = (const float*)d_in[0];
    const float* target  = (const float*)d_in[1];
    float* out = (float*)d_out;

    crps_fused_kernel<<<NBLOCKS, TPB>>>(samples, target, out);
}